// round 8
// baseline (speedup 1.0000x reference)
#include <cuda_runtime.h>
#include <cuda_bf16.h>

// ConvThreshold: scale-adaptive 5x5 Gaussian conv over ReLU(bev_map) + mask.
//   conv[b,y,x] = sum relu(map[y+dy,x+dx]) * e1^(dy^2+dx^2),  e1 = exp(-1/(2 s^2+eps))
// Separable weights; each thread: 4 x-pixels x 2 y-rows via LDS.128.
// R8: scale prefetch + weight exp BEFORE the barrier; batched tile LDGs (MLP);
//     launch_bounds(256,6) for occupancy.

#define BH 768
#define BW 768
#define NB 4

#define TX 32
#define TY 8
#define VEC 4
#define RPT 2                    // output rows per thread
#define OW (TX * VEC)            // 128 output cols per block
#define OH (TY * RPT)            // 16 output rows per block
#define TILE_W (OW + 8)          // 136 floats (x-origin = bx-4), 16B aligned
#define TILE_H (OH + 4)          // 20 rows   (y-origin = by-2)
#define TILE_W4 (TILE_W / 4)     // 34
#define NLOAD (TILE_H * TILE_W4) // 680 float4 loads per block

__global__ __launch_bounds__(TX * TY, 6) void conv_threshold_kernel(
    const float* __restrict__ bev_map,
    const float* __restrict__ bev_scale,
    float* __restrict__ out_conv,
    float* __restrict__ out_mask)
{
    __shared__ float tile[TILE_H][TILE_W];

    const int bx = blockIdx.x * OW;
    const int by = blockIdx.y * OH;
    const int b  = blockIdx.z;
    const int tx = threadIdx.x;
    const int ty = threadIdx.y;
    const int tid = ty * TX + tx;

    const float* m = bev_map + (size_t)b * BH * BW;

    // ---- prefetch per-thread scales FIRST (DRAM latency overlaps tile fill) ----
    const int gx  = bx + tx * VEC;
    const int oy0 = by + ty * RPT;
    const size_t obase = (size_t)b * BH * BW + (size_t)oy0 * BW + gx;
    const float4 s4a = __ldg(reinterpret_cast<const float4*>(&bev_scale[obase]));
    const float4 s4b = __ldg(reinterpret_cast<const float4*>(&bev_scale[obase + BW]));

    // ---- cooperative tile load, batched for MLP: 3 predicated float4s ----
    {
        float4 vv[3];
        int sy[3], sx4[3];
        bool pred[3];
#pragma unroll
        for (int it = 0; it < 3; it++) {
            const int idx = tid + it * (TX * TY);
            const bool act = (idx < NLOAD);
            const int ly  = idx / TILE_W4;
            const int lxv = idx - ly * TILE_W4;
            const int gy  = by + ly - 2;
            const int gx0 = bx - 4 + lxv * 4;
            sy[it] = ly; sx4[it] = lxv; pred[it] = act;

            float4 v = make_float4(0.f, 0.f, 0.f, 0.f);
            if (act) {
                if ((unsigned)gy < BH && gx0 >= 0 && gx0 + 3 < BW) {
                    v = *reinterpret_cast<const float4*>(&m[(size_t)gy * BW + gx0]);
                } else {
                    const float* row = &m[(size_t)gy * BW];
                    v.x = ((unsigned)gy < BH && (unsigned)(gx0 + 0) < BW) ? row[gx0 + 0] : 0.0f;
                    v.y = ((unsigned)gy < BH && (unsigned)(gx0 + 1) < BW) ? row[gx0 + 1] : 0.0f;
                    v.z = ((unsigned)gy < BH && (unsigned)(gx0 + 2) < BW) ? row[gx0 + 2] : 0.0f;
                    v.w = ((unsigned)gy < BH && (unsigned)(gx0 + 3) < BW) ? row[gx0 + 3] : 0.0f;
                }
            }
            vv[it] = v;
        }
#pragma unroll
        for (int it = 0; it < 3; it++) {
            if (pred[it]) {
                float4 v = vv[it];
                v.x = fmaxf(v.x, 0.0f); v.y = fmaxf(v.y, 0.0f);
                v.z = fmaxf(v.z, 0.0f); v.w = fmaxf(v.w, 0.0f);
                *reinterpret_cast<float4*>(&tile[sy[it]][sx4[it] * 4]) = v;
            }
        }
    }

    // ---- weight exp math BEFORE the barrier (overlaps STS drain / bar wait) ----
    float e1w[RPT][VEC], e4w[RPT][VEC];
#pragma unroll
    for (int o = 0; o < RPT; o++) {
        const float4 s4 = (o == 0) ? s4a : s4b;
#pragma unroll
        for (int p = 0; p < VEC; p++) {
            const float s = (p == 0) ? s4.x : (p == 1) ? s4.y : (p == 2) ? s4.z : s4.w;
            const float e1 = __expf(-1.0f / (2.0f * s * s + 1e-6f));
            const float e2 = e1 * e1;
            e1w[o][p] = e1;
            e4w[o][p] = e2 * e2;
        }
    }

    __syncthreads();

    // ---- per-thread: 4 x-pixels (gx..gx+3) x 2 y-rows (oy0, oy0+1) ----
    float acc[RPT][VEC] = {{0.0f, 0.0f, 0.0f, 0.0f}, {0.0f, 0.0f, 0.0f, 0.0f}};

    const int c0 = tx * VEC;       // pixel p tap dx -> v[2+p+dx] (tile x-origin bx-4)
    const int r0 = ty * RPT;       // tile row of out row0's dy=0 tap

#pragma unroll
    for (int r = 0; r < 5 + RPT - 1; r++) {   // 6 tile rows
        const float4 a  = *reinterpret_cast<const float4*>(&tile[r0 + r][c0]);
        const float4 bq = *reinterpret_cast<const float4*>(&tile[r0 + r][c0 + 4]);
        const float4 c  = *reinterpret_cast<const float4*>(&tile[r0 + r][c0 + 8]);
        const float v[12] = {a.x, a.y, a.z, a.w, bq.x, bq.y, bq.z, bq.w,
                             c.x, c.y, c.z, c.w};

        // weight-independent x-pair sums, shared by both output rows
        float a04[VEC], a13[VEC], a2[VEC];
#pragma unroll
        for (int p = 0; p < VEC; p++) {
            a04[p] = v[2 + p] + v[6 + p];
            a13[p] = v[3 + p] + v[5 + p];
            a2[p]  = v[4 + p];
        }

#pragma unroll
        for (int o = 0; o < RPT; o++) {
            const int k = r - o;               // tap index for output row o
            if (k >= 0 && k <= 4) {
                const int ady = (k < 2) ? (2 - k) : (k - 2);   // |dy| in {0,1,2}
#pragma unroll
                for (int p = 0; p < VEC; p++) {
                    const float rs = fmaf(e4w[o][p], a04[p],
                                     fmaf(e1w[o][p], a13[p], a2[p]));
                    if (ady == 0)      acc[o][p] += rs;
                    else if (ady == 1) acc[o][p] = fmaf(rs, e1w[o][p], acc[o][p]);
                    else               acc[o][p] = fmaf(rs, e4w[o][p], acc[o][p]);
                }
            }
        }
    }

#pragma unroll
    for (int o = 0; o < RPT; o++) {
        float4 conv4 = make_float4(acc[o][0], acc[o][1], acc[o][2], acc[o][3]);
        float4 mask4 = make_float4(acc[o][0] >= 0.5f ? 1.0f : 0.0f,
                                   acc[o][1] >= 0.5f ? 1.0f : 0.0f,
                                   acc[o][2] >= 0.5f ? 1.0f : 0.0f,
                                   acc[o][3] >= 0.5f ? 1.0f : 0.0f);
        *reinterpret_cast<float4*>(&out_conv[obase + (size_t)o * BW]) = conv4;
        *reinterpret_cast<float4*>(&out_mask[obase + (size_t)o * BW]) = mask4;
    }
}

extern "C" void kernel_launch(void* const* d_in, const int* in_sizes, int n_in,
                              void* d_out, int out_size)
{
    const float* bev_map   = (const float*)d_in[0];
    const float* bev_scale = (const float*)d_in[1];
    float* out = (float*)d_out;

    float* out_conv = out;
    float* out_mask = out + (size_t)NB * BH * BW;

    dim3 block(TX, TY);
    dim3 grid(BW / OW, BH / OH, NB);
    conv_threshold_kernel<<<grid, block>>>(bev_map, bev_scale, out_conv, out_mask);
}

// round 9
// speedup vs baseline: 1.0304x; 1.0304x over previous
#include <cuda_runtime.h>
#include <cuda_bf16.h>

// ConvThreshold: scale-adaptive 5x5 Gaussian conv over ReLU(bev_map) + mask.
//   conv[b,y,x] = sum relu(map[y+dy,x+dx]) * e1^(dy^2+dx^2),  e1 = exp(-1/(2 s^2+eps))
// Separable weights; each thread: 4 x-pixels x 2 y-rows via LDS.128.
// R9 = R7 body + (scale prefetch & exp before barrier) + minCTA 6.

#define BH 768
#define BW 768
#define NB 4

#define TX 32
#define TY 8
#define VEC 4
#define RPT 2                    // output rows per thread
#define OW (TX * VEC)            // 128 output cols per block
#define OH (TY * RPT)            // 16 output rows per block
#define TILE_W (OW + 8)          // 136 floats (x-origin = bx-4), 16B aligned
#define TILE_H (OH + 4)          // 20 rows   (y-origin = by-2)
#define TILE_W4 (TILE_W / 4)     // 34

__global__ __launch_bounds__(TX * TY, 6) void conv_threshold_kernel(
    const float* __restrict__ bev_map,
    const float* __restrict__ bev_scale,
    float* __restrict__ out_conv,
    float* __restrict__ out_mask)
{
    __shared__ float tile[TILE_H][TILE_W];

    const int bx = blockIdx.x * OW;
    const int by = blockIdx.y * OH;
    const int b  = blockIdx.z;
    const int tx = threadIdx.x;
    const int ty = threadIdx.y;
    const int tid = ty * TX + tx;

    const float* m = bev_map + (size_t)b * BH * BW;

    // ---- prefetch per-thread scales FIRST (DRAM latency overlaps tile fill) ----
    const int gx  = bx + tx * VEC;
    const int oy0 = by + ty * RPT;
    const size_t obase = (size_t)b * BH * BW + (size_t)oy0 * BW + gx;
    const float4 s4a = __ldg(reinterpret_cast<const float4*>(&bev_scale[obase]));
    const float4 s4b = __ldg(reinterpret_cast<const float4*>(&bev_scale[obase + BW]));

    // ---- cooperative tile load: [by-2, by+OH+2) x [bx-4, bx+OW+4), ReLU'd ----
    for (int idx = tid; idx < TILE_H * TILE_W4; idx += TX * TY) {
        const int ly  = idx / TILE_W4;
        const int lxv = idx - ly * TILE_W4;
        const int gy  = by + ly - 2;
        const int gx0 = bx - 4 + lxv * 4;

        float4 v;
        if ((unsigned)gy < BH && gx0 >= 0 && gx0 + 3 < BW) {
            v = *reinterpret_cast<const float4*>(&m[(size_t)gy * BW + gx0]);
        } else {
            const float* row = &m[(size_t)gy * BW];
            v.x = ((unsigned)gy < BH && (unsigned)(gx0 + 0) < BW) ? row[gx0 + 0] : 0.0f;
            v.y = ((unsigned)gy < BH && (unsigned)(gx0 + 1) < BW) ? row[gx0 + 1] : 0.0f;
            v.z = ((unsigned)gy < BH && (unsigned)(gx0 + 2) < BW) ? row[gx0 + 2] : 0.0f;
            v.w = ((unsigned)gy < BH && (unsigned)(gx0 + 3) < BW) ? row[gx0 + 3] : 0.0f;
        }
        v.x = fmaxf(v.x, 0.0f); v.y = fmaxf(v.y, 0.0f);
        v.z = fmaxf(v.z, 0.0f); v.w = fmaxf(v.w, 0.0f);
        *reinterpret_cast<float4*>(&tile[ly][lxv * 4]) = v;
    }

    // ---- weight exp math BEFORE the barrier (overlaps STS drain / bar wait) ----
    float e1w[RPT][VEC], e4w[RPT][VEC];
#pragma unroll
    for (int o = 0; o < RPT; o++) {
        const float4 s4 = (o == 0) ? s4a : s4b;
#pragma unroll
        for (int p = 0; p < VEC; p++) {
            const float s = (p == 0) ? s4.x : (p == 1) ? s4.y : (p == 2) ? s4.z : s4.w;
            const float e1 = __expf(-1.0f / (2.0f * s * s + 1e-6f));
            const float e2 = e1 * e1;
            e1w[o][p] = e1;
            e4w[o][p] = e2 * e2;
        }
    }

    __syncthreads();

    // ---- per-thread: 4 x-pixels (gx..gx+3) x 2 y-rows (oy0, oy0+1) ----
    float acc[RPT][VEC] = {{0.0f, 0.0f, 0.0f, 0.0f}, {0.0f, 0.0f, 0.0f, 0.0f}};

    const int c0 = tx * VEC;       // pixel p tap dx -> v[2+p+dx] (tile x-origin bx-4)
    const int r0 = ty * RPT;       // tile row of out row0's dy=0 tap

#pragma unroll
    for (int r = 0; r < 5 + RPT - 1; r++) {   // 6 tile rows
        const float4 a  = *reinterpret_cast<const float4*>(&tile[r0 + r][c0]);
        const float4 bq = *reinterpret_cast<const float4*>(&tile[r0 + r][c0 + 4]);
        const float4 c  = *reinterpret_cast<const float4*>(&tile[r0 + r][c0 + 8]);
        const float v[12] = {a.x, a.y, a.z, a.w, bq.x, bq.y, bq.z, bq.w,
                             c.x, c.y, c.z, c.w};

        // weight-independent x-pair sums, shared by both output rows
        float a04[VEC], a13[VEC], a2[VEC];
#pragma unroll
        for (int p = 0; p < VEC; p++) {
            a04[p] = v[2 + p] + v[6 + p];
            a13[p] = v[3 + p] + v[5 + p];
            a2[p]  = v[4 + p];
        }

#pragma unroll
        for (int o = 0; o < RPT; o++) {
            const int k = r - o;               // tap index for output row o
            if (k >= 0 && k <= 4) {
                const int ady = (k < 2) ? (2 - k) : (k - 2);   // |dy| in {0,1,2}
#pragma unroll
                for (int p = 0; p < VEC; p++) {
                    const float rs = fmaf(e4w[o][p], a04[p],
                                     fmaf(e1w[o][p], a13[p], a2[p]));
                    if (ady == 0)      acc[o][p] += rs;
                    else if (ady == 1) acc[o][p] = fmaf(rs, e1w[o][p], acc[o][p]);
                    else               acc[o][p] = fmaf(rs, e4w[o][p], acc[o][p]);
                }
            }
        }
    }

#pragma unroll
    for (int o = 0; o < RPT; o++) {
        float4 conv4 = make_float4(acc[o][0], acc[o][1], acc[o][2], acc[o][3]);
        float4 mask4 = make_float4(acc[o][0] >= 0.5f ? 1.0f : 0.0f,
                                   acc[o][1] >= 0.5f ? 1.0f : 0.0f,
                                   acc[o][2] >= 0.5f ? 1.0f : 0.0f,
                                   acc[o][3] >= 0.5f ? 1.0f : 0.0f);
        *reinterpret_cast<float4*>(&out_conv[obase + (size_t)o * BW]) = conv4;
        *reinterpret_cast<float4*>(&out_mask[obase + (size_t)o * BW]) = mask4;
    }
}

extern "C" void kernel_launch(void* const* d_in, const int* in_sizes, int n_in,
                              void* d_out, int out_size)
{
    const float* bev_map   = (const float*)d_in[0];
    const float* bev_scale = (const float*)d_in[1];
    float* out = (float*)d_out;

    float* out_conv = out;
    float* out_mask = out + (size_t)NB * BH * BW;

    dim3 block(TX, TY);
    dim3 grid(BW / OW, BH / OH, NB);
    conv_threshold_kernel<<<grid, block>>>(bev_map, bev_scale, out_conv, out_mask);
}

// round 10
// speedup vs baseline: 1.1274x; 1.0942x over previous
#include <cuda_runtime.h>
#include <cuda_bf16.h>

// ConvThreshold: scale-adaptive 5x5 Gaussian conv over ReLU(bev_map) + mask.
//   conv[b,y,x] = sum relu(map[y+dy,x+dx]) * e1^(dy^2+dx^2),  e1 = exp(-1/(2 s^2+eps))
// Separable weights. R10: single-wave grid (576 blocks = 148 SMs x 4 CTAs),
// RPT=4 rows/thread, interior fast-path tile fill, pre-barrier scale/exp.

#define BH 768
#define BW 768
#define NB 4

#define TX 32
#define TY 8
#define VEC 4
#define RPT 4                    // output rows per thread
#define OW (TX * VEC)            // 128 output cols per block
#define OH (TY * RPT)            // 32 output rows per block
#define TILE_W (OW + 8)          // 136 floats (x-origin = bx-4)
#define TILE_H (OH + 4)          // 36 rows   (y-origin = by-2)
#define TILE_W4 (TILE_W / 4)     // 34
#define NLOAD (TILE_H * TILE_W4) // 1224 float4s per block

__global__ __launch_bounds__(TX * TY, 4) void conv_threshold_kernel(
    const float* __restrict__ bev_map,
    const float* __restrict__ bev_scale,
    float* __restrict__ out_conv,
    float* __restrict__ out_mask)
{
    __shared__ float tile[TILE_H][TILE_W];

    const int bx = blockIdx.x * OW;
    const int by = blockIdx.y * OH;
    const int b  = blockIdx.z;
    const int tx = threadIdx.x;
    const int ty = threadIdx.y;
    const int tid = ty * TX + tx;

    const float* m = bev_map + (size_t)b * BH * BW;

    // ---- prefetch per-thread scales FIRST (DRAM latency overlaps tile fill) ----
    const int gx  = bx + tx * VEC;
    const int oy0 = by + ty * RPT;
    const size_t obase = (size_t)b * BH * BW + (size_t)oy0 * BW + gx;
    float4 s4[RPT];
#pragma unroll
    for (int o = 0; o < RPT; o++)
        s4[o] = __ldg(reinterpret_cast<const float4*>(&bev_scale[obase + (size_t)o * BW]));

    // ---- cooperative tile fill: [by-2, by+OH+2) x [bx-4, bx+OW+4), ReLU'd ----
    const bool interior = (bx >= 4) && (bx + OW + 4 <= BW) &&
                          (by >= 2) && (by + OH + 2 <= BH);
    if (interior) {
#pragma unroll
        for (int it = 0; it < 5; it++) {
            const int idx = tid + it * (TX * TY);
            if (idx < NLOAD) {
                const int ly  = idx / TILE_W4;
                const int lxv = idx - ly * TILE_W4;
                float4 v = *reinterpret_cast<const float4*>(
                    &m[(size_t)(by + ly - 2) * BW + (bx - 4 + lxv * 4)]);
                v.x = fmaxf(v.x, 0.0f); v.y = fmaxf(v.y, 0.0f);
                v.z = fmaxf(v.z, 0.0f); v.w = fmaxf(v.w, 0.0f);
                *reinterpret_cast<float4*>(&tile[ly][lxv * 4]) = v;
            }
        }
    } else {
        for (int idx = tid; idx < NLOAD; idx += TX * TY) {
            const int ly  = idx / TILE_W4;
            const int lxv = idx - ly * TILE_W4;
            const int gy  = by + ly - 2;
            const int gx0 = bx - 4 + lxv * 4;
            float4 v;
            if ((unsigned)gy < BH && gx0 >= 0 && gx0 + 3 < BW) {
                v = *reinterpret_cast<const float4*>(&m[(size_t)gy * BW + gx0]);
            } else {
                const float* row = &m[(size_t)gy * BW];
                v.x = ((unsigned)gy < BH && (unsigned)(gx0 + 0) < BW) ? row[gx0 + 0] : 0.0f;
                v.y = ((unsigned)gy < BH && (unsigned)(gx0 + 1) < BW) ? row[gx0 + 1] : 0.0f;
                v.z = ((unsigned)gy < BH && (unsigned)(gx0 + 2) < BW) ? row[gx0 + 2] : 0.0f;
                v.w = ((unsigned)gy < BH && (unsigned)(gx0 + 3) < BW) ? row[gx0 + 3] : 0.0f;
            }
            v.x = fmaxf(v.x, 0.0f); v.y = fmaxf(v.y, 0.0f);
            v.z = fmaxf(v.z, 0.0f); v.w = fmaxf(v.w, 0.0f);
            *reinterpret_cast<float4*>(&tile[ly][lxv * 4]) = v;
        }
    }

    // ---- weight exp math BEFORE the barrier (overlaps STS drain / bar wait) ----
    float e1w[RPT][VEC], e4w[RPT][VEC];
#pragma unroll
    for (int o = 0; o < RPT; o++) {
#pragma unroll
        for (int p = 0; p < VEC; p++) {
            const float s = (p == 0) ? s4[o].x : (p == 1) ? s4[o].y
                          : (p == 2) ? s4[o].z : s4[o].w;
            const float e1 = __expf(-1.0f / (2.0f * s * s + 1e-6f));
            const float e2 = e1 * e1;
            e1w[o][p] = e1;
            e4w[o][p] = e2 * e2;
        }
    }

    __syncthreads();

    // ---- per-thread: 4 x-pixels (gx..gx+3) x 4 y-rows (oy0..oy0+3) ----
    float acc[RPT][VEC];
#pragma unroll
    for (int o = 0; o < RPT; o++)
#pragma unroll
        for (int p = 0; p < VEC; p++) acc[o][p] = 0.0f;

    const int c0 = tx * VEC;       // pixel p tap dx -> v[2+p+dx] (tile x-origin bx-4)
    const int r0 = ty * RPT;       // tile row of out row0's dy=0 tap

#pragma unroll
    for (int r = 0; r < 5 + RPT - 1; r++) {   // 8 tile rows
        const float4 a  = *reinterpret_cast<const float4*>(&tile[r0 + r][c0]);
        const float4 bq = *reinterpret_cast<const float4*>(&tile[r0 + r][c0 + 4]);
        const float4 c  = *reinterpret_cast<const float4*>(&tile[r0 + r][c0 + 8]);
        const float v[12] = {a.x, a.y, a.z, a.w, bq.x, bq.y, bq.z, bq.w,
                             c.x, c.y, c.z, c.w};

        // weight-independent x-pair sums, shared by all output rows
        float a04[VEC], a13[VEC], a2[VEC];
#pragma unroll
        for (int p = 0; p < VEC; p++) {
            a04[p] = v[2 + p] + v[6 + p];
            a13[p] = v[3 + p] + v[5 + p];
            a2[p]  = v[4 + p];
        }

#pragma unroll
        for (int o = 0; o < RPT; o++) {
            const int k = r - o;               // tap index for output row o
            if (k >= 0 && k <= 4) {
                const int ady = (k < 2) ? (2 - k) : (k - 2);   // |dy| in {0,1,2}
#pragma unroll
                for (int p = 0; p < VEC; p++) {
                    const float rs = fmaf(e4w[o][p], a04[p],
                                     fmaf(e1w[o][p], a13[p], a2[p]));
                    if (ady == 0)      acc[o][p] += rs;
                    else if (ady == 1) acc[o][p] = fmaf(rs, e1w[o][p], acc[o][p]);
                    else               acc[o][p] = fmaf(rs, e4w[o][p], acc[o][p]);
                }
            }
        }
    }

#pragma unroll
    for (int o = 0; o < RPT; o++) {
        float4 conv4 = make_float4(acc[o][0], acc[o][1], acc[o][2], acc[o][3]);
        float4 mask4 = make_float4(acc[o][0] >= 0.5f ? 1.0f : 0.0f,
                                   acc[o][1] >= 0.5f ? 1.0f : 0.0f,
                                   acc[o][2] >= 0.5f ? 1.0f : 0.0f,
                                   acc[o][3] >= 0.5f ? 1.0f : 0.0f);
        *reinterpret_cast<float4*>(&out_conv[obase + (size_t)o * BW]) = conv4;
        *reinterpret_cast<float4*>(&out_mask[obase + (size_t)o * BW]) = mask4;
    }
}

extern "C" void kernel_launch(void* const* d_in, const int* in_sizes, int n_in,
                              void* d_out, int out_size)
{
    const float* bev_map   = (const float*)d_in[0];
    const float* bev_scale = (const float*)d_in[1];
    float* out = (float*)d_out;

    float* out_conv = out;
    float* out_mask = out + (size_t)NB * BH * BW;

    dim3 block(TX, TY);
    dim3 grid(BW / OW, BH / OH, NB);   // 6 x 24 x 4 = 576 blocks = one wave @ occ 4
    conv_threshold_kernel<<<grid, block>>>(bev_map, bev_scale, out_conv, out_mask);
}